// round 1
// baseline (speedup 1.0000x reference)
#include <cuda_runtime.h>

// Problem constants (from reference): 50000 nodes, 256 feats, 400000 edges,
// DIFF_T=1.0, N_SEG=4 (t_seg=0.25), N_TERMS=8.
#define NN_MAX 50000
#define DF 256
#define DF4 (DF / 4)
#define NE_MAX 400000

// Scratch (allocation-free: static device globals).
__device__ int   g_cnt[NN_MAX + 1];
__device__ int   g_rowptr[NN_MAX + 1];
__device__ int   g_fill[NN_MAX];
__device__ int   g_sums[64];
__device__ int   g_offs[64];
__device__ int   g_cols[NE_MAX];
__device__ float g_vals[NE_MAX];
__device__ float g_deg[NN_MAX];
__device__ float g_term0[(size_t)NN_MAX * DF];
__device__ float g_term1[(size_t)NN_MAX * DF];

// ---------------------------------------------------------------------------
// CSR build: count + degree
// ---------------------------------------------------------------------------
__global__ void count_deg_kernel(const int* __restrict__ rows,
                                 const float* __restrict__ vals, int ne) {
    int e = blockIdx.x * blockDim.x + threadIdx.x;
    if (e < ne) {
        int r = rows[e];
        atomicAdd(&g_cnt[r], 1);
        atomicAdd(&g_deg[r], vals[e]);
    }
}

// Exclusive scan over g_cnt[0..n) -> g_rowptr, 3-kernel (chunked) version.
__global__ void scan1_kernel(int n) {
    __shared__ int sh[1024];
    int tid = threadIdx.x;
    int i = blockIdx.x * 1024 + tid;
    int v = (i < n) ? g_cnt[i] : 0;
    sh[tid] = v;
    __syncthreads();
    for (int off = 1; off < 1024; off <<= 1) {
        int t = (tid >= off) ? sh[tid - off] : 0;
        __syncthreads();
        sh[tid] += t;
        __syncthreads();
    }
    if (i < n) g_rowptr[i] = sh[tid] - v;   // exclusive within chunk
    if (tid == 1023) g_sums[blockIdx.x] = sh[1023];
}

__global__ void scan2_kernel(int nchunks) {
    if (blockIdx.x == 0 && threadIdx.x == 0) {
        int run = 0;
        for (int b = 0; b < nchunks; b++) {
            int s = g_sums[b];
            g_offs[b] = run;
            run += s;
        }
    }
}

__global__ void scan3_kernel(int n) {
    int i = blockIdx.x * 1024 + threadIdx.x;
    if (i < n) g_rowptr[i] += g_offs[blockIdx.x];
}

__global__ void scatter_kernel(const int* __restrict__ rows,
                               const int* __restrict__ cols,
                               const float* __restrict__ vals, int ne) {
    int e = blockIdx.x * blockDim.x + threadIdx.x;
    if (e < ne) {
        int r = rows[e];
        int pos = atomicAdd(&g_fill[r], 1);
        g_cols[pos] = cols[e];
        g_vals[pos] = vals[e];
    }
}

// ---------------------------------------------------------------------------
// Fused Taylor step:
//   t_new = coef * (deg[r] * src[r] - sum_e val_e * src[col_e])
//   dst[r] = t_new ; acc[r] += t_new
// One row handled by 64 threads, float4 per thread (256 feats).
// blockDim = (64, 4) -> 4 rows per block.
// ---------------------------------------------------------------------------
__global__ void taylor_kernel(const float4* __restrict__ src,
                              float4* __restrict__ dst,
                              float4* __restrict__ acc,
                              float coef, int nn) {
    int r = blockIdx.x * 4 + threadIdx.y;
    if (r >= nn) return;
    int f = threadIdx.x;  // 0..63
    int start = g_rowptr[r];
    int end = g_rowptr[r + 1];

    float sx = 0.f, sy = 0.f, sz = 0.f, sw = 0.f;
    for (int e = start; e < end; e++) {
        int c = g_cols[e];        // warp-broadcast
        float w = g_vals[e];      // warp-broadcast
        float4 v = src[(size_t)c * DF4 + f];  // coalesced 1KB row gather
        sx = fmaf(w, v.x, sx);
        sy = fmaf(w, v.y, sy);
        sz = fmaf(w, v.z, sz);
        sw = fmaf(w, v.w, sw);
    }

    float d = g_deg[r];
    size_t idx = (size_t)r * DF4 + f;
    float4 m = src[idx];
    float4 t;
    t.x = coef * fmaf(d, m.x, -sx);
    t.y = coef * fmaf(d, m.y, -sy);
    t.z = coef * fmaf(d, m.z, -sz);
    t.w = coef * fmaf(d, m.w, -sw);
    dst[idx] = t;
    float4 a = acc[idx];
    a.x += t.x;
    a.y += t.y;
    a.z += t.z;
    a.w += t.w;
    acc[idx] = a;
}

// ---------------------------------------------------------------------------
// Launch
// ---------------------------------------------------------------------------
extern "C" void kernel_launch(void* const* d_in, const int* in_sizes, int n_in,
                              void* d_out, int out_size) {
    const float* x  = (const float*)d_in[0];
    const int*   er = (const int*)d_in[1];
    const int*   ec = (const int*)d_in[2];
    const float* ev = (const float*)d_in[3];
    float* out = (float*)d_out;

    int ne = in_sizes[1];
    int nn = in_sizes[0] / DF;

    void *p_cnt, *p_deg, *p_fill, *p_rowptr, *p_t0, *p_t1;
    cudaGetSymbolAddress(&p_cnt, g_cnt);
    cudaGetSymbolAddress(&p_deg, g_deg);
    cudaGetSymbolAddress(&p_fill, g_fill);
    cudaGetSymbolAddress(&p_rowptr, g_rowptr);
    cudaGetSymbolAddress(&p_t0, g_term0);
    cudaGetSymbolAddress(&p_t1, g_term1);

    // --- CSR build (captured each replay; ~tens of microseconds) ---
    cudaMemsetAsync(p_cnt, 0, (size_t)(nn + 1) * sizeof(int));
    cudaMemsetAsync(p_deg, 0, (size_t)nn * sizeof(float));
    count_deg_kernel<<<(ne + 255) / 256, 256>>>(er, ev, ne);

    int nscan = nn + 1;
    int nchunks = (nscan + 1023) / 1024;
    scan1_kernel<<<nchunks, 1024>>>(nscan);
    scan2_kernel<<<1, 32>>>(nchunks);
    scan3_kernel<<<nchunks, 1024>>>(nscan);

    cudaMemcpyAsync(p_fill, p_rowptr, (size_t)nn * sizeof(int),
                    cudaMemcpyDeviceToDevice);
    scatter_kernel<<<(ne + 255) / 256, 256>>>(er, ec, ev, ne);

    // --- expm action: acc lives in d_out ---
    size_t xbytes = (size_t)nn * DF * sizeof(float);
    cudaMemcpyAsync(out, x, xbytes, cudaMemcpyDeviceToDevice);

    float* bufs[2] = {(float*)p_t0, (float*)p_t1};
    const float t_seg = 0.25f;  // DIFF_T / N_SEG
    int nblocks = (nn + 3) / 4;
    dim3 bd(64, 4);

    for (int seg = 0; seg < 4; seg++) {
        // term = y (y == acc == out after previous segment; x for segment 0)
        cudaMemcpyAsync(p_t0, seg == 0 ? (const void*)x : (const void*)out,
                        xbytes, cudaMemcpyDeviceToDevice);
        int cur = 0;
        for (int k = 1; k <= 8; k++) {
            float coef = -t_seg / (float)k;
            taylor_kernel<<<nblocks, bd>>>((const float4*)bufs[cur],
                                           (float4*)bufs[cur ^ 1],
                                           (float4*)out, coef, nn);
            cur ^= 1;
        }
    }
}

// round 2
// speedup vs baseline: 1.3235x; 1.3235x over previous
#include <cuda_runtime.h>

// Problem constants (from reference): 50000 nodes, 256 feats, 400000 edges,
// DIFF_T=1.0, N_SEG=4 (t_seg=0.25), N_TERMS=8.
#define NN_MAX 50000
#define DF 256
#define DF4 (DF / 4)
#define NE_MAX 400000

// Scratch (allocation-free: static device globals).
__device__ int   g_cnt[NN_MAX + 1];
__device__ int   g_rowptr[NN_MAX + 1];
__device__ int   g_fill[NN_MAX];
__device__ int   g_sums[64];
__device__ int   g_offs[64];
__device__ int   g_cols[NE_MAX];
__device__ float g_vals[NE_MAX];
__device__ float g_deg[NN_MAX];
__device__ float g_term0[(size_t)NN_MAX * DF];
__device__ float g_term1[(size_t)NN_MAX * DF];

// ---------------------------------------------------------------------------
// CSR build: count + degree
// ---------------------------------------------------------------------------
__global__ void count_deg_kernel(const int* __restrict__ rows,
                                 const float* __restrict__ vals, int ne) {
    int e = blockIdx.x * blockDim.x + threadIdx.x;
    if (e < ne) {
        int r = rows[e];
        atomicAdd(&g_cnt[r], 1);
        atomicAdd(&g_deg[r], vals[e]);
    }
}

// Exclusive scan over g_cnt[0..n) -> g_rowptr, 3-kernel (chunked) version.
__global__ void scan1_kernel(int n) {
    __shared__ int sh[1024];
    int tid = threadIdx.x;
    int i = blockIdx.x * 1024 + tid;
    int v = (i < n) ? g_cnt[i] : 0;
    sh[tid] = v;
    __syncthreads();
    for (int off = 1; off < 1024; off <<= 1) {
        int t = (tid >= off) ? sh[tid - off] : 0;
        __syncthreads();
        sh[tid] += t;
        __syncthreads();
    }
    if (i < n) g_rowptr[i] = sh[tid] - v;   // exclusive within chunk
    if (tid == 1023) g_sums[blockIdx.x] = sh[1023];
}

__global__ void scan2_kernel(int nchunks) {
    if (blockIdx.x == 0 && threadIdx.x == 0) {
        int run = 0;
        for (int b = 0; b < nchunks; b++) {
            int s = g_sums[b];
            g_offs[b] = run;
            run += s;
        }
    }
}

__global__ void scan3_kernel(int n) {
    int i = blockIdx.x * 1024 + threadIdx.x;
    if (i < n) g_rowptr[i] += g_offs[blockIdx.x];
}

__global__ void scatter_kernel(const int* __restrict__ rows,
                               const int* __restrict__ cols,
                               const float* __restrict__ vals, int ne) {
    int e = blockIdx.x * blockDim.x + threadIdx.x;
    if (e < ne) {
        int r = rows[e];
        int pos = atomicAdd(&g_fill[r], 1);
        g_cols[pos] = cols[e];
        g_vals[pos] = vals[e];
    }
}

// ---------------------------------------------------------------------------
// Horner step:
//   dst[r] = y[r] + coef * ( deg[r]*src[r] - sum_e val_e * src[col_e] )
// One row handled by 32 threads (one warp): each thread owns float4 lanes
// f and f+32 of the 64 float4-lanes per row. 8 rows per 256-thread block.
// Inner loop unrolled x2 over edges -> 4 independent float4 gathers in
// flight per thread (MLP), col/val loads are warp-uniform broadcasts.
// ---------------------------------------------------------------------------
__global__ void horner_kernel(const float4* __restrict__ src,
                              const float4* __restrict__ y,
                              float4* __restrict__ dst,
                              float coef, int nn) {
    int r = blockIdx.x * 8 + threadIdx.y;
    if (r >= nn) return;
    int f = threadIdx.x;  // 0..31
    int start = g_rowptr[r];
    int end = g_rowptr[r + 1];

    float4 s0 = make_float4(0.f, 0.f, 0.f, 0.f);
    float4 s1 = make_float4(0.f, 0.f, 0.f, 0.f);

    int e = start;
    for (; e + 1 < end; e += 2) {
        int   c0 = g_cols[e];
        int   c1 = g_cols[e + 1];
        float w0 = g_vals[e];
        float w1 = g_vals[e + 1];
        const float4* p0 = src + (size_t)c0 * DF4;
        const float4* p1 = src + (size_t)c1 * DF4;
        float4 a0 = p0[f];
        float4 a1 = p0[f + 32];
        float4 b0 = p1[f];
        float4 b1 = p1[f + 32];
        s0.x = fmaf(w0, a0.x, s0.x); s0.y = fmaf(w0, a0.y, s0.y);
        s0.z = fmaf(w0, a0.z, s0.z); s0.w = fmaf(w0, a0.w, s0.w);
        s1.x = fmaf(w0, a1.x, s1.x); s1.y = fmaf(w0, a1.y, s1.y);
        s1.z = fmaf(w0, a1.z, s1.z); s1.w = fmaf(w0, a1.w, s1.w);
        s0.x = fmaf(w1, b0.x, s0.x); s0.y = fmaf(w1, b0.y, s0.y);
        s0.z = fmaf(w1, b0.z, s0.z); s0.w = fmaf(w1, b0.w, s0.w);
        s1.x = fmaf(w1, b1.x, s1.x); s1.y = fmaf(w1, b1.y, s1.y);
        s1.z = fmaf(w1, b1.z, s1.z); s1.w = fmaf(w1, b1.w, s1.w);
    }
    if (e < end) {
        int   c0 = g_cols[e];
        float w0 = g_vals[e];
        const float4* p0 = src + (size_t)c0 * DF4;
        float4 a0 = p0[f];
        float4 a1 = p0[f + 32];
        s0.x = fmaf(w0, a0.x, s0.x); s0.y = fmaf(w0, a0.y, s0.y);
        s0.z = fmaf(w0, a0.z, s0.z); s0.w = fmaf(w0, a0.w, s0.w);
        s1.x = fmaf(w0, a1.x, s1.x); s1.y = fmaf(w0, a1.y, s1.y);
        s1.z = fmaf(w0, a1.z, s1.z); s1.w = fmaf(w0, a1.w, s1.w);
    }

    float d = g_deg[r];
    size_t i0 = (size_t)r * DF4 + f;
    size_t i1 = i0 + 32;
    float4 m0 = src[i0];
    float4 m1 = src[i1];
    float4 y0 = y[i0];
    float4 y1 = y[i1];
    float4 o0, o1;
    o0.x = fmaf(coef, fmaf(d, m0.x, -s0.x), y0.x);
    o0.y = fmaf(coef, fmaf(d, m0.y, -s0.y), y0.y);
    o0.z = fmaf(coef, fmaf(d, m0.z, -s0.z), y0.z);
    o0.w = fmaf(coef, fmaf(d, m0.w, -s0.w), y0.w);
    o1.x = fmaf(coef, fmaf(d, m1.x, -s1.x), y1.x);
    o1.y = fmaf(coef, fmaf(d, m1.y, -s1.y), y1.y);
    o1.z = fmaf(coef, fmaf(d, m1.z, -s1.z), y1.z);
    o1.w = fmaf(coef, fmaf(d, m1.w, -s1.w), y1.w);
    dst[i0] = o0;
    dst[i1] = o1;
}

// ---------------------------------------------------------------------------
// Launch
// ---------------------------------------------------------------------------
extern "C" void kernel_launch(void* const* d_in, const int* in_sizes, int n_in,
                              void* d_out, int out_size) {
    const float* x  = (const float*)d_in[0];
    const int*   er = (const int*)d_in[1];
    const int*   ec = (const int*)d_in[2];
    const float* ev = (const float*)d_in[3];
    float* out = (float*)d_out;

    int ne = in_sizes[1];
    int nn = in_sizes[0] / DF;

    void *p_cnt, *p_deg, *p_fill, *p_rowptr, *p_t0, *p_t1;
    cudaGetSymbolAddress(&p_cnt, g_cnt);
    cudaGetSymbolAddress(&p_deg, g_deg);
    cudaGetSymbolAddress(&p_fill, g_fill);
    cudaGetSymbolAddress(&p_rowptr, g_rowptr);
    cudaGetSymbolAddress(&p_t0, g_term0);
    cudaGetSymbolAddress(&p_t1, g_term1);
    float* t0 = (float*)p_t0;
    float* t1 = (float*)p_t1;

    // --- CSR build (captured each replay) ---
    cudaMemsetAsync(p_cnt, 0, (size_t)(nn + 1) * sizeof(int));
    cudaMemsetAsync(p_deg, 0, (size_t)nn * sizeof(float));
    count_deg_kernel<<<(ne + 255) / 256, 256>>>(er, ev, ne);

    int nscan = nn + 1;
    int nchunks = (nscan + 1023) / 1024;
    scan1_kernel<<<nchunks, 1024>>>(nscan);
    scan2_kernel<<<1, 32>>>(nchunks);
    scan3_kernel<<<nchunks, 1024>>>(nscan);

    cudaMemcpyAsync(p_fill, p_rowptr, (size_t)nn * sizeof(int),
                    cudaMemcpyDeviceToDevice);
    scatter_kernel<<<(ne + 255) / 256, 256>>>(er, ec, ev, ne);

    // --- expm action: 4 segments, Horner form, 3-buffer rotation ---
    // Segment s: z = y; for k=8..1: z <- y + (-ts/k) L z ; y_next = z
    // Writes ping-pong p,q (8 writes -> final lands in q).
    const float ts = 0.25f;  // DIFF_T / N_SEG
    int nblocks = (nn + 7) / 8;
    dim3 bd(32, 8);

    const float* y = x;
    for (int seg = 0; seg < 4; seg++) {
        float* p = t0;
        float* q = (seg & 1) ? out : ((seg == 2) ? t1 : t1);
        // seg0 -> q=t1, seg1 -> q=out, seg2 -> q=t1, seg3 -> q=out
        if (seg == 1 || seg == 3) q = out; else q = t1;

        const float* src = y;
        float* dstbufs[2] = {p, q};
        for (int k = 8; k >= 1; k--) {
            float coef = -ts / (float)k;
            float* dst = dstbufs[(8 - k) & 1];  // k=8 -> p, k=7 -> q, ...
            horner_kernel<<<nblocks, bd>>>((const float4*)src,
                                           (const float4*)y,
                                           (float4*)dst, coef, nn);
            src = dst;
        }
        y = src;  // final dst == q
    }
    // After seg3, result is in `out`.
}